// round 4
// baseline (speedup 1.0000x reference)
#include <cuda_runtime.h>
#include <math.h>

// Problem constants:
// text_vec  [8,2048,1024]  -> A1 [M=16384, K=1024]
// labels_vec[4096,768]
// W_proj    [768,1024]
// b_proj    [768]
// out       [8,2048,768]   -> [16384, 768]

#define BM 128
#define BN 128
#define BK 8

// Scratch (no cudaMalloc allowed)
__device__ float g_t[16384 * 768];            // projected text, 50 MB
__device__ float g_P[16384 * 4096];           // exp(alpha), 268 MB

// sigmoid -> threshold -> exp, matching reference semantics:
//   a = sigmoid(x); a = (a < 0.4) ? 0 : a; P = exp(a)   (exp(0)=1)
__device__ __forceinline__ float sig_thresh_exp(float x) {
    float u = __expf(-x);
    float a = __fdividef(1.0f, 1.0f + u);
    return (a < 0.4f) ? 1.0f : __expf(a);
}

// ---------------------------------------------------------------------------
// NT GEMM: A[M,K] row-major (K contig), B[N,K] row-major (K contig)
// C[m,n] = sum_k A[m,k]*B[n,k]  (+ epilogue)
// EPI = 0: C += bias[n], store
// EPI = 1: C = sig_thresh_exp(C), store
// ---------------------------------------------------------------------------
template <int EPI>
__global__ __launch_bounds__(256, 2)
void gemm_nt_kernel(const float* __restrict__ A, const float* __restrict__ B,
                    const float* __restrict__ bias, float* __restrict__ C,
                    int N, int K)
{
    __shared__ float As[2][BK][BM + 4];
    __shared__ float Bs[2][BK][BN + 4];

    const int tid     = threadIdx.x;
    const int rowBase = blockIdx.y * BM;
    const int colBase = blockIdx.x * BN;

    // Global load mapping: 2 threads per row, float4 along K
    const int arow = tid >> 1;
    const int kseg = (tid & 1) << 2;

    const float* Ap = A + (rowBase + arow) * K + kseg;
    const float* Bp = B + (colBase + arow) * K + kseg;

    float4 aR = *(const float4*)Ap;
    float4 bR = *(const float4*)Bp;

    As[0][kseg + 0][arow] = aR.x; As[0][kseg + 1][arow] = aR.y;
    As[0][kseg + 2][arow] = aR.z; As[0][kseg + 3][arow] = aR.w;
    Bs[0][kseg + 0][arow] = bR.x; Bs[0][kseg + 1][arow] = bR.y;
    Bs[0][kseg + 2][arow] = bR.z; Bs[0][kseg + 3][arow] = bR.w;
    __syncthreads();

    const int tx = (tid & 15) << 3;   // col offset in tile
    const int ty = (tid >> 4) << 3;   // row offset in tile

    float acc[8][8] = {};
    float aF[8], bF[8];

    const int nT  = K / BK;
    int       buf = 0;

    for (int t = 0; t < nT; ++t) {
        if (t + 1 < nT) {
            aR = *(const float4*)(Ap + (t + 1) * BK);
            bR = *(const float4*)(Bp + (t + 1) * BK);
        }
        #pragma unroll
        for (int k = 0; k < BK; ++k) {
            *(float4*)&aF[0] = *(const float4*)&As[buf][k][ty];
            *(float4*)&aF[4] = *(const float4*)&As[buf][k][ty + 4];
            *(float4*)&bF[0] = *(const float4*)&Bs[buf][k][tx];
            *(float4*)&bF[4] = *(const float4*)&Bs[buf][k][tx + 4];
            #pragma unroll
            for (int i = 0; i < 8; ++i)
                #pragma unroll
                for (int j = 0; j < 8; ++j)
                    acc[i][j] = fmaf(aF[i], bF[j], acc[i][j]);
        }
        if (t + 1 < nT) {
            buf ^= 1;
            As[buf][kseg + 0][arow] = aR.x; As[buf][kseg + 1][arow] = aR.y;
            As[buf][kseg + 2][arow] = aR.z; As[buf][kseg + 3][arow] = aR.w;
            Bs[buf][kseg + 0][arow] = bR.x; Bs[buf][kseg + 1][arow] = bR.y;
            Bs[buf][kseg + 2][arow] = bR.z; Bs[buf][kseg + 3][arow] = bR.w;
            __syncthreads();
        }
    }

    // Epilogue
    float bv[8];
    if (EPI == 0) {
        #pragma unroll
        for (int j = 0; j < 8; ++j) bv[j] = bias[colBase + tx + j];
    }

    #pragma unroll
    for (int i = 0; i < 8; ++i) {
        float* Crow = C + (rowBase + ty + i) * N + colBase + tx;
        float o[8];
        #pragma unroll
        for (int j = 0; j < 8; ++j) {
            float v = acc[i][j];
            if (EPI == 0) v += bv[j];
            else          v  = sig_thresh_exp(v);
            o[j] = v;
        }
        float4 v0 = make_float4(o[0], o[1], o[2], o[3]);
        float4 v1 = make_float4(o[4], o[5], o[6], o[7]);
        *(float4*)(Crow)     = v0;
        *(float4*)(Crow + 4) = v1;
    }
}

// ---------------------------------------------------------------------------
// NN GEMM with inline row-sum normalization:
// A = P [M,K] row-major (K contig), B = labels [K,N] row-major (N contig)
// C[m,n] = (sum_k A[m,k]*B[k,n]) / (sum_k A[m,k])
// Each row-block sees ALL K of its A rows -> Z computed during A loads.
// ---------------------------------------------------------------------------
__global__ __launch_bounds__(256, 2)
void gemm_nn_div_kernel(const float* __restrict__ A, const float* __restrict__ B,
                        float* __restrict__ C, int N, int K)
{
    __shared__ float As[2][BK][BM + 4];
    __shared__ float Bs[2][BK][BN + 4];
    __shared__ float zrow[BM];

    const int tid     = threadIdx.x;
    const int rowBase = blockIdx.y * BM;
    const int colBase = blockIdx.x * BN;

    const int arow = tid >> 1;
    const int kseg = (tid & 1) << 2;
    const float* Ap = A + (rowBase + arow) * K + kseg;

    const int brow = tid >> 5;            // 0..7 (k within tile)
    const int bcol = (tid & 31) << 2;     // 0..124
    const float* Bp = B + brow * N + colBase + bcol;

    float zpart = 0.0f;

    float4 aR = *(const float4*)Ap;
    float4 bR = *(const float4*)Bp;
    zpart += (aR.x + aR.y) + (aR.z + aR.w);

    As[0][kseg + 0][arow] = aR.x; As[0][kseg + 1][arow] = aR.y;
    As[0][kseg + 2][arow] = aR.z; As[0][kseg + 3][arow] = aR.w;
    *(float4*)&Bs[0][brow][bcol] = bR;
    __syncthreads();

    const int tx = (tid & 15) << 3;
    const int ty = (tid >> 4) << 3;

    float acc[8][8] = {};
    float aF[8], bF[8];

    const int nT  = K / BK;
    int       buf = 0;

    for (int t = 0; t < nT; ++t) {
        if (t + 1 < nT) {
            aR = *(const float4*)(Ap + (t + 1) * BK);
            bR = *(const float4*)(Bp + (t + 1) * BK * N);
            zpart += (aR.x + aR.y) + (aR.z + aR.w);
        }
        #pragma unroll
        for (int k = 0; k < BK; ++k) {
            *(float4*)&aF[0] = *(const float4*)&As[buf][k][ty];
            *(float4*)&aF[4] = *(const float4*)&As[buf][k][ty + 4];
            *(float4*)&bF[0] = *(const float4*)&Bs[buf][k][tx];
            *(float4*)&bF[4] = *(const float4*)&Bs[buf][k][tx + 4];
            #pragma unroll
            for (int i = 0; i < 8; ++i)
                #pragma unroll
                for (int j = 0; j < 8; ++j)
                    acc[i][j] = fmaf(aF[i], bF[j], acc[i][j]);
        }
        if (t + 1 < nT) {
            buf ^= 1;
            As[buf][kseg + 0][arow] = aR.x; As[buf][kseg + 1][arow] = aR.y;
            As[buf][kseg + 2][arow] = aR.z; As[buf][kseg + 3][arow] = aR.w;
            *(float4*)&Bs[buf][brow][bcol] = bR;
            __syncthreads();
        }
    }

    // Pair-reduce Z: tid and tid^1 hold the two K-halves of row `arow`
    zpart += __shfl_xor_sync(0xffffffffu, zpart, 1);
    if ((tid & 1) == 0) zrow[arow] = zpart;
    __syncthreads();

    #pragma unroll
    for (int i = 0; i < 8; ++i) {
        float invz = 1.0f / zrow[ty + i];
        float* Crow = C + (rowBase + ty + i) * N + colBase + tx;
        float4 v0 = make_float4(acc[i][0] * invz, acc[i][1] * invz,
                                acc[i][2] * invz, acc[i][3] * invz);
        float4 v1 = make_float4(acc[i][4] * invz, acc[i][5] * invz,
                                acc[i][6] * invz, acc[i][7] * invz);
        *(float4*)(Crow)     = v0;
        *(float4*)(Crow + 4) = v1;
    }
}

extern "C" void kernel_launch(void* const* d_in, const int* in_sizes, int n_in,
                              void* d_out, int out_size)
{
    const float* text   = (const float*)d_in[0];   // [16384, 1024]
    const float* labels = (const float*)d_in[1];   // [4096, 768]
    const float* W      = (const float*)d_in[2];   // [768, 1024]
    const float* bias   = (const float*)d_in[3];   // [768]
    float*       out    = (float*)d_out;           // [16384, 768]

    float *t_buf = nullptr, *P_buf = nullptr;
    cudaGetSymbolAddress((void**)&t_buf, g_t);
    cudaGetSymbolAddress((void**)&P_buf, g_P);

    // GEMM1: t = text @ W^T + b   (M=16384, N=768, K=1024, NT)
    gemm_nt_kernel<0><<<dim3(768 / BN, 16384 / BM), 256>>>(text, W, bias, t_buf, 768, 1024);

    // GEMM2: P = exp(thresh(sigmoid(t @ labels^T)))  (M=16384, N=4096, K=768, NT)
    gemm_nt_kernel<1><<<dim3(4096 / BN, 16384 / BM), 256>>>(t_buf, labels, nullptr, P_buf, 4096, 768);

    // GEMM3: out = (P @ labels) / rowsum(P)  (M=16384, N=768, K=4096, NN)
    gemm_nn_div_kernel<<<dim3(768 / BN, 16384 / BM), 256>>>(P_buf, labels, out, 768, 4096);
}

// round 11
// speedup vs baseline: 1.6227x; 1.6227x over previous
#include <cuda_runtime.h>
#include <cuda_bf16.h>
#include <cstdint>
#include <math.h>

using bf16 = __nv_bfloat16;

// ===========================================================================
// AmplifierAttention, sm_103-portable tensor path (mma.sync bf16, no tcgen05)
// All GEMMs: C = A[M,K] * B[N,K]^T via 2-way bf16 split, 3 products
//   G1: t = text @ W^T + b          (K=1024, N=768)  -> t hi/lo planes
//   G2: P = sigthresh(t @ labels^T) (K=768,  N=4096) -> P hi/lo planes
//   G3: out = (P @ labels) / rowsumP (K=4096, N=768) -> fp32
// ===========================================================================

// ---------------- scratch -------------------------------------------------
__device__ bf16 g_x0[16384ull * 1024], g_x1[16384ull * 1024];
__device__ bf16 g_w0[768 * 1024],      g_w1[768 * 1024];
__device__ bf16 g_t0[16384ull * 768],  g_t1[16384ull * 768];
__device__ bf16 g_lb0[4096 * 768],     g_lb1[4096 * 768];
__device__ bf16 g_lt0[768 * 4096],     g_lt1[768 * 4096];
__device__ bf16 g_Phi[16384ull * 4096], g_Plo[16384ull * 4096];

// ---------------- helpers -------------------------------------------------
__device__ __forceinline__ uint32_t smem_u32(const void* p) {
    uint32_t a;
    asm("{ .reg .u64 t; cvta.to.shared.u64 t, %1; cvt.u32.u64 %0, t; }" : "=r"(a) : "l"(p));
    return a;
}

#define CP16(s, g)  asm volatile("cp.async.cg.shared.global [%0], [%1], 16;" :: "r"(s), "l"(g))
#define CPCOMMIT()  asm volatile("cp.async.commit_group;" ::: "memory")
#define CPWAIT0()   asm volatile("cp.async.wait_group 0;" ::: "memory")
#define CPWAIT1()   asm volatile("cp.async.wait_group 1;" ::: "memory")

#define LDM4(r, addr)                                                        \
    asm volatile("ldmatrix.sync.aligned.m8n8.x4.shared.b16 {%0,%1,%2,%3}, [%4];" \
        : "=r"((r)[0]), "=r"((r)[1]), "=r"((r)[2]), "=r"((r)[3]) : "r"(addr))

#define MMA(c, a, b0, b1)                                                    \
    asm volatile("mma.sync.aligned.m16n8k16.row.col.f32.bf16.bf16.f32 "      \
        "{%0,%1,%2,%3}, {%4,%5,%6,%7}, {%8,%9}, {%0,%1,%2,%3};"              \
        : "+f"((c)[0]), "+f"((c)[1]), "+f"((c)[2]), "+f"((c)[3])             \
        : "r"((a)[0]), "r"((a)[1]), "r"((a)[2]), "r"((a)[3]), "r"(b0), "r"(b1))

__device__ __forceinline__ float sum_bf162(uint32_t u) {
    __nv_bfloat162 h = *reinterpret_cast<__nv_bfloat162*>(&u);
    float2 f = __bfloat1622float2(h);
    return f.x + f.y;
}

__device__ __forceinline__ void split2(float x, bf16& hi, bf16& lo) {
    hi = __float2bfloat16(x);
    lo = __float2bfloat16(x - __bfloat162float(hi));
}

// sigmoid -> threshold -> exp (exp(0)=1 below threshold)
__device__ __forceinline__ float sig_thresh_exp(float x) {
    float u = __expf(-x);
    float a = __fdividef(1.0f, 1.0f + u);
    return (a < 0.4f) ? 1.0f : __expf(a);
}

// ---------------- prep kernels --------------------------------------------
__global__ void prep_text_kernel(const float* __restrict__ x) {
    size_t i = (size_t)blockIdx.x * 256 + threadIdx.x;
    if (i >= 16384ull * 1024) return;
    bf16 h, l; split2(x[i], h, l);
    g_x0[i] = h; g_x1[i] = l;
}
__global__ void prep_w_kernel(const float* __restrict__ w) {
    int i = blockIdx.x * 256 + threadIdx.x;
    if (i >= 768 * 1024) return;
    bf16 h, l; split2(w[i], h, l);
    g_w0[i] = h; g_w1[i] = l;
}
__global__ void prep_labels_kernel(const float* __restrict__ lab) {
    int i = blockIdx.x * 256 + threadIdx.x;
    if (i >= 4096 * 768) return;
    bf16 h, l; split2(lab[i], h, l);
    g_lb0[i] = h; g_lb1[i] = l;
    int r = i / 768, e = i % 768;
    int j = e * 4096 + r;
    g_lt0[j] = h; g_lt1[j] = l;
}

// ===========================================================================
// Unified NT mma kernel. Block 128x128, 8 warps (4M x 2N), warp tile 32x64.
// BK=64, cp.async double-buffered. Rows padded to 72 bf16 (144B, ldmatrix-
// conflict-free). 3 products: Ahi*Bhi + Ahi*Blo + Alo*Bhi.
// EPI 1: +bias -> split bf16 hi/lo.  EPI 2: sig_thresh_exp -> split hi/lo.
// EPI 3: inline rowsum(A) -> divide, fp32 out.
// ===========================================================================
template <int KDIM, int EPI>
__global__ __launch_bounds__(256, 1)
void mma_nt_kernel(const bf16* __restrict__ Ahi, const bf16* __restrict__ Alo,
                   const bf16* __restrict__ Bhi, const bf16* __restrict__ Blo,
                   const float* __restrict__ bias,
                   bf16* __restrict__ oHi, bf16* __restrict__ oLo,
                   float* __restrict__ oF, int ldC)
{
    extern __shared__ char smem[];
    const uint32_t sb = smem_u32(smem);
    float* zrow = (float*)smem;                     // [0, 512)
    constexpr uint32_t TILE = 128 * 72 * 2;         // 18432 B
    constexpr uint32_t STG  = 4 * TILE;             // 73728 B
    constexpr uint32_t DATA = 1024;
    constexpr int NST = KDIM / 64;

    const int tid = threadIdx.x, lane = tid & 31, wid = tid >> 5;
    const int warpM = wid & 3, warpN = wid >> 2;
    const int rowBase = blockIdx.y * 128, colBase = blockIdx.x * 128;

    const int lrow = tid >> 1, lkh = tid & 1;       // loader: 2 thr/row
    const size_t aOff = (size_t)(rowBase + lrow) * KDIM + lkh * 32;
    const size_t bOff = (size_t)(colBase + lrow) * KDIM + lkh * 32;
    const uint32_t ldst = (uint32_t)((lrow * 72 + lkh * 32) * 2);

    auto issue = [&](int st) {
        const uint32_t dst = sb + DATA + (uint32_t)(st & 1) * STG + ldst;
        const bf16* gA0 = Ahi + aOff + st * 64;
        const bf16* gA1 = Alo + aOff + st * 64;
        const bf16* gB0 = Bhi + bOff + st * 64;
        const bf16* gB1 = Blo + bOff + st * 64;
        #pragma unroll
        for (int s = 0; s < 4; ++s) {
            CP16(dst + 0 * TILE + s * 16, gA0 + s * 8);
            CP16(dst + 1 * TILE + s * 16, gA1 + s * 8);
            CP16(dst + 2 * TILE + s * 16, gB0 + s * 8);
            CP16(dst + 3 * TILE + s * 16, gB1 + s * 8);
        }
    };

    float acc[2][8][4];
    #pragma unroll
    for (int i = 0; i < 2; ++i)
        #pragma unroll
        for (int j = 0; j < 8; ++j)
            #pragma unroll
            for (int q = 0; q < 4; ++q) acc[i][j][q] = 0.0f;
    float zp[4] = {0.f, 0.f, 0.f, 0.f};

    // ldmatrix lane -> (matrix, row-in-matrix) offsets
    const int lm_r = ((lane >> 3) & 1) * 8 + (lane & 7);  // row offset
    const int lm_c = (lane >> 4) * 8;                     // col offset (k)

    issue(0); CPCOMMIT();

    for (int st = 0; st < NST; ++st) {
        if (st + 1 < NST) { issue(st + 1); CPCOMMIT(); CPWAIT1(); }
        else              { CPWAIT0(); }
        __syncthreads();

        const uint32_t base = sb + DATA + (uint32_t)(st & 1) * STG;
        #pragma unroll
        for (int kk = 0; kk < 4; ++kk) {
            uint32_t ah[2][4], al[2][4];
            #pragma unroll
            for (int mi = 0; mi < 2; ++mi) {
                uint32_t ra = base +
                    (uint32_t)(((warpM * 32 + mi * 16 + lm_r) * 72 + kk * 16 + lm_c) * 2);
                LDM4(ah[mi], ra);
                LDM4(al[mi], ra + TILE);
            }
            if (EPI == 3 && warpN == 0) {
                #pragma unroll
                for (int mi = 0; mi < 2; ++mi)
                    #pragma unroll
                    for (int r = 0; r < 4; ++r)
                        zp[mi * 2 + (r & 1)] += sum_bf162(ah[mi][r]) + sum_bf162(al[mi][r]);
            }
            #pragma unroll
            for (int nb = 0; nb < 4; ++nb) {
                uint32_t bh[4], bl[4];
                uint32_t rb = base + 2 * TILE +
                    (uint32_t)(((warpN * 64 + nb * 16 + lm_r) * 72 + kk * 16 + lm_c) * 2);
                LDM4(bh, rb);
                LDM4(bl, rb + TILE);
                #pragma unroll
                for (int mi = 0; mi < 2; ++mi) {
                    #pragma unroll
                    for (int ns = 0; ns < 2; ++ns) {
                        float* c = acc[mi][nb * 2 + ns];
                        MMA(c, ah[mi], bh[ns], bh[ns + 2]);
                        MMA(c, ah[mi], bl[ns], bl[ns + 2]);
                        MMA(c, al[mi], bh[ns], bh[ns + 2]);
                    }
                }
            }
        }
        __syncthreads();
    }

    if (EPI == 3) {
        if (warpN == 0) {
            #pragma unroll
            for (int j = 0; j < 4; ++j) {
                zp[j] += __shfl_xor_sync(0xffffffffu, zp[j], 1);
                zp[j] += __shfl_xor_sync(0xffffffffu, zp[j], 2);
            }
            if ((lane & 3) == 0) {
                #pragma unroll
                for (int j = 0; j < 4; ++j)
                    zrow[warpM * 32 + j * 8 + (lane >> 2)] = zp[j];
            }
        }
        __syncthreads();
    }

    // ---------------- epilogue ----------------
    #pragma unroll
    for (int mi = 0; mi < 2; ++mi) {
        const int r0 = warpM * 32 + mi * 16 + (lane >> 2);
        #pragma unroll
        for (int nj = 0; nj < 8; ++nj) {
            const int col = colBase + warpN * 64 + nj * 8 + 2 * (lane & 3);
            const float* c = acc[mi][nj];
            if (EPI == 1) {
                float b0 = bias[col], b1 = bias[col + 1];
                #pragma unroll
                for (int h = 0; h < 2; ++h) {       // h=0: rows r0, h=1: r0+8
                    size_t o = (size_t)(rowBase + r0 + h * 8) * ldC + col;
                    bf16 h0, l0, h1, l1;
                    split2(c[h * 2 + 0] + b0, h0, l0);
                    split2(c[h * 2 + 1] + b1, h1, l1);
                    *(__nv_bfloat162*)(oHi + o) = __nv_bfloat162(h0, h1);
                    *(__nv_bfloat162*)(oLo + o) = __nv_bfloat162(l0, l1);
                }
            } else if (EPI == 2) {
                #pragma unroll
                for (int h = 0; h < 2; ++h) {
                    size_t o = (size_t)(rowBase + r0 + h * 8) * ldC + col;
                    bf16 h0, l0, h1, l1;
                    split2(sig_thresh_exp(c[h * 2 + 0]), h0, l0);
                    split2(sig_thresh_exp(c[h * 2 + 1]), h1, l1);
                    *(__nv_bfloat162*)(oHi + o) = __nv_bfloat162(h0, h1);
                    *(__nv_bfloat162*)(oLo + o) = __nv_bfloat162(l0, l1);
                }
            } else {
                #pragma unroll
                for (int h = 0; h < 2; ++h) {
                    const float invz = 1.0f / zrow[r0 + h * 8];
                    size_t o = (size_t)(rowBase + r0 + h * 8) * ldC + col;
                    float2 v = make_float2(c[h * 2 + 0] * invz, c[h * 2 + 1] * invz);
                    *(float2*)(oF + o) = v;
                }
            }
        }
    }
}

// ===========================================================================
extern "C" void kernel_launch(void* const* d_in, const int* in_sizes, int n_in,
                              void* d_out, int out_size)
{
    const float* text   = (const float*)d_in[0];   // [16384,1024]
    const float* labels = (const float*)d_in[1];   // [4096,768]
    const float* W      = (const float*)d_in[2];   // [768,1024]
    const float* bias   = (const float*)d_in[3];   // [768]
    float*       out    = (float*)d_out;           // [16384,768]

    constexpr int SMEM = 1024 + 2 * (4 * 128 * 72 * 2);   // 148480
    cudaFuncSetAttribute(mma_nt_kernel<1024, 1>, cudaFuncAttributeMaxDynamicSharedMemorySize, SMEM);
    cudaFuncSetAttribute(mma_nt_kernel<768, 2>,  cudaFuncAttributeMaxDynamicSharedMemorySize, SMEM);
    cudaFuncSetAttribute(mma_nt_kernel<4096, 3>, cudaFuncAttributeMaxDynamicSharedMemorySize, SMEM);

    bf16 *x0, *x1, *w0, *w1, *t0, *t1, *lb0, *lb1, *lt0, *lt1, *Phi, *Plo;
    cudaGetSymbolAddress((void**)&x0, g_x0);  cudaGetSymbolAddress((void**)&x1, g_x1);
    cudaGetSymbolAddress((void**)&w0, g_w0);  cudaGetSymbolAddress((void**)&w1, g_w1);
    cudaGetSymbolAddress((void**)&t0, g_t0);  cudaGetSymbolAddress((void**)&t1, g_t1);
    cudaGetSymbolAddress((void**)&lb0, g_lb0); cudaGetSymbolAddress((void**)&lb1, g_lb1);
    cudaGetSymbolAddress((void**)&lt0, g_lt0); cudaGetSymbolAddress((void**)&lt1, g_lt1);
    cudaGetSymbolAddress((void**)&Phi, g_Phi); cudaGetSymbolAddress((void**)&Plo, g_Plo);

    prep_text_kernel<<<(int)((16384ull * 1024 + 255) / 256), 256>>>(text);
    prep_w_kernel<<<(768 * 1024 + 255) / 256, 256>>>(W);
    prep_labels_kernel<<<(4096 * 768 + 255) / 256, 256>>>(labels);

    // G1: t = text @ W^T + b
    mma_nt_kernel<1024, 1><<<dim3(6, 128), 256, SMEM>>>(
        x0, x1, w0, w1, bias, t0, t1, nullptr, 768);
    // G2: P = sig_thresh_exp(t @ labels^T)
    mma_nt_kernel<768, 2><<<dim3(32, 128), 256, SMEM>>>(
        t0, t1, lb0, lb1, nullptr, Phi, Plo, nullptr, 4096);
    // G3: out = (P @ labels) / rowsum(P)
    mma_nt_kernel<4096, 3><<<dim3(6, 128), 256, SMEM>>>(
        Phi, Plo, lt0, lt1, nullptr, nullptr, nullptr, out, 768);
}